// round 2
// baseline (speedup 1.0000x reference)
#include <cuda_runtime.h>
#include <cuda_bf16.h>
#include <math.h>
#include <stdint.h>

// Problem constants (fixed by the dataset)
#define NNODES 100000
#define NEDGES 1600000
#define DIN 128
#define DH  128
#define DOUT 64

// ---------------- device scratch (no allocations allowed) ----------------
__device__ __align__(16) static float g_bufA[(size_t)NNODES * DH];   // aggregate buffer / m3
__device__ __align__(16) static float g_bufB[(size_t)NNODES * DH];   // layer output buffer
__device__ __align__(16) static float g_bufG[(size_t)NNODES * DOUT]; // g = h2 @ W3
__device__ static int   g_rowptr[NNODES + 1];
__device__ static int   g_cursor[NNODES + 1];
__device__ static int   g_colidx[NEDGES];
__device__ static int   g_outdeg[NNODES];
__device__ static int   g_indeg[NNODES];
__device__ static float g_norm_src[NNODES];
__device__ static float g_norm_dst[NNODES];
__device__ static int   g_blksums[256];

// ---------------- CSR build ----------------
__global__ void zero_deg_kernel(int n) {
    int i = blockIdx.x * blockDim.x + threadIdx.x;
    if (i < n) { g_outdeg[i] = 0; g_indeg[i] = 0; }
}

__global__ void deg_kernel(const int* __restrict__ src, const int* __restrict__ dst, int E) {
    int e = blockIdx.x * blockDim.x + threadIdx.x;
    if (e < E) {
        atomicAdd(&g_outdeg[src[e]], 1);
        atomicAdd(&g_indeg[dst[e]], 1);
    }
}

__global__ void norm_kernel(int n) {
    int i = blockIdx.x * blockDim.x + threadIdx.x;
    if (i < n) {
        int od = g_outdeg[i]; if (od < 1) od = 1;
        int id = g_indeg[i];  if (id < 1) id = 1;
        g_norm_src[i] = rsqrtf((float)od);
        g_norm_dst[i] = rsqrtf((float)id);
    }
}

// scan pass 1: per-block (1024 elems) exclusive scan of g_indeg -> g_rowptr, totals -> g_blksums
__global__ void scan1_kernel(int n) {
    __shared__ int warp_sums[8];
    int base = blockIdx.x * 1024;
    int t = threadIdx.x;
    int idx0 = base + t * 4;
    int v[4];
#pragma unroll
    for (int i = 0; i < 4; i++) { int idx = idx0 + i; v[i] = (idx < n) ? g_indeg[idx] : 0; }
    int s = v[0] + v[1] + v[2] + v[3];
    int lane = t & 31, wid = t >> 5;
    int ss = s;
#pragma unroll
    for (int o = 1; o < 32; o <<= 1) { int x = __shfl_up_sync(0xFFFFFFFFu, ss, o); if (lane >= o) ss += x; }
    if (lane == 31) warp_sums[wid] = ss;
    __syncthreads();
    if (wid == 0) {
        int w = (lane < 8) ? warp_sums[lane] : 0;
#pragma unroll
        for (int o = 1; o < 8; o <<= 1) { int x = __shfl_up_sync(0xFFFFFFFFu, w, o); if (lane >= o) w += x; }
        if (lane < 8) warp_sums[lane] = w;
    }
    __syncthreads();
    int excl = ss - s + ((wid > 0) ? warp_sums[wid - 1] : 0);
    int run = excl;
#pragma unroll
    for (int i = 0; i < 4; i++) { int idx = idx0 + i; if (idx < n) g_rowptr[idx] = run; run += v[i]; }
    if (t == 255) g_blksums[blockIdx.x] = warp_sums[7];
}

// scan pass 2: exclusive scan of block sums (nb <= 128), single block of 128 threads
__global__ void scan2_kernel(int nb) {
    __shared__ int ws[4];
    int t = threadIdx.x;
    int v = (t < nb) ? g_blksums[t] : 0;
    int lane = t & 31, wid = t >> 5;
    int s = v;
#pragma unroll
    for (int o = 1; o < 32; o <<= 1) { int x = __shfl_up_sync(0xFFFFFFFFu, s, o); if (lane >= o) s += x; }
    if (lane == 31) ws[wid] = s;
    __syncthreads();
    if (wid == 0) {
        int w = (lane < 4) ? ws[lane] : 0;
#pragma unroll
        for (int o = 1; o < 4; o <<= 1) { int x = __shfl_up_sync(0xFFFFFFFFu, w, o); if (lane >= o) w += x; }
        if (lane < 4) ws[lane] = w;
    }
    __syncthreads();
    int excl = s - v + ((wid > 0) ? ws[wid - 1] : 0);
    if (t < nb) g_blksums[t] = excl;
}

// scan pass 3: add block offsets, mirror to cursor, close row_ptr
__global__ void scan3_kernel(int n, int E) {
    int idx = blockIdx.x * blockDim.x + threadIdx.x;
    if (idx < n) {
        int v = g_rowptr[idx] + g_blksums[idx >> 10];
        g_rowptr[idx] = v;
        g_cursor[idx] = v;
    }
    if (idx == n) g_rowptr[n] = E;
}

__global__ void scatter_kernel(const int* __restrict__ src, const int* __restrict__ dst, int E) {
    int e = blockIdx.x * blockDim.x + threadIdx.x;
    if (e < E) {
        int d = dst[e];
        int p = atomicAdd(&g_cursor[d], 1);
        g_colidx[p] = src[e];
    }
}

// ---------------- SpMM: out[v] = norm_dst[v] * sum_{u in N_in(v)} (scale(u) * x[u]) ----------------
template<int D, bool SRCSCALE>
__global__ __launch_bounds__(256) void spmm_kernel(
    const float* __restrict__ x, const float* __restrict__ sscale,
    float* __restrict__ out, int n)
{
    int warp = (blockIdx.x * 256 + threadIdx.x) >> 5;
    int lane = threadIdx.x & 31;
    if (warp >= n) return;
    int beg = __ldg(&g_rowptr[warp]);
    int end = __ldg(&g_rowptr[warp + 1]);
    float dsc = __ldg(&g_norm_dst[warp]);

    if (D == 128) {
        const float4* xp = (const float4*)x;
        float4 a0 = {0.f,0.f,0.f,0.f}, a1 = {0.f,0.f,0.f,0.f};
        int e = beg;
        for (; e + 1 < end; e += 2) {
            int u0 = __ldg(&g_colidx[e]);
            int u1 = __ldg(&g_colidx[e + 1]);
            float s0 = SRCSCALE ? __ldg(&sscale[u0]) : 1.0f;
            float s1 = SRCSCALE ? __ldg(&sscale[u1]) : 1.0f;
            float4 v0 = __ldg(&xp[(size_t)u0 * 32 + lane]);
            float4 v1 = __ldg(&xp[(size_t)u1 * 32 + lane]);
            a0.x += s0 * v0.x; a0.y += s0 * v0.y; a0.z += s0 * v0.z; a0.w += s0 * v0.w;
            a1.x += s1 * v1.x; a1.y += s1 * v1.y; a1.z += s1 * v1.z; a1.w += s1 * v1.w;
        }
        if (e < end) {
            int u0 = __ldg(&g_colidx[e]);
            float s0 = SRCSCALE ? __ldg(&sscale[u0]) : 1.0f;
            float4 v0 = __ldg(&xp[(size_t)u0 * 32 + lane]);
            a0.x += s0 * v0.x; a0.y += s0 * v0.y; a0.z += s0 * v0.z; a0.w += s0 * v0.w;
        }
        float4 r;
        r.x = (a0.x + a1.x) * dsc; r.y = (a0.y + a1.y) * dsc;
        r.z = (a0.z + a1.z) * dsc; r.w = (a0.w + a1.w) * dsc;
        ((float4*)out)[(size_t)warp * 32 + lane] = r;
    } else { // D == 64
        const float2* xp = (const float2*)x;
        float2 a0 = {0.f,0.f}, a1 = {0.f,0.f};
        int e = beg;
        for (; e + 1 < end; e += 2) {
            int u0 = __ldg(&g_colidx[e]);
            int u1 = __ldg(&g_colidx[e + 1]);
            float s0 = SRCSCALE ? __ldg(&sscale[u0]) : 1.0f;
            float s1 = SRCSCALE ? __ldg(&sscale[u1]) : 1.0f;
            float2 v0 = __ldg(&xp[(size_t)u0 * 32 + lane]);
            float2 v1 = __ldg(&xp[(size_t)u1 * 32 + lane]);
            a0.x += s0 * v0.x; a0.y += s0 * v0.y;
            a1.x += s1 * v1.x; a1.y += s1 * v1.y;
        }
        if (e < end) {
            int u0 = __ldg(&g_colidx[e]);
            float s0 = SRCSCALE ? __ldg(&sscale[u0]) : 1.0f;
            float2 v0 = __ldg(&xp[(size_t)u0 * 32 + lane]);
            a0.x += s0 * v0.x; a0.y += s0 * v0.y;
        }
        float2 r;
        r.x = (a0.x + a1.x) * dsc; r.y = (a0.y + a1.y) * dsc;
        ((float2*)out)[(size_t)warp * 32 + lane] = r;
    }
}

// ---------------- tf32 tensor-core GEMM ----------------
// C[M x BN] = A[M x 128] @ W[128 x BN]; EPI_RELU: C = relu(acc+bias)*rowscale
// Whole K=128 staged in smem. As: [128][132] (m-major, pad 132 -> frag LDS bank = 4g+t,
// bijective over the warp). Bs: [128 k][136] (k-major, pad 136 -> frag LDS bank = 8t+g).
// mma.m16n8k8 tf32 fragments: a0=(g,t) a1=(g+8,t) a2=(g,t+4) a3=(g+8,t+4);
// b0=(k=t,n=g) b1=(k=t+4,n=g); c0..c3=(g,2t),(g,2t+1),(g+8,2t),(g+8,2t+1).
#define AS_STRIDE 132
#define BS_STRIDE 136
#define GEMM_SMEM_BYTES ((128*AS_STRIDE + 128*BS_STRIDE) * 4)

__device__ __forceinline__ uint32_t f2tf(float x) {
    uint32_t r; asm("cvt.rna.tf32.f32 %0, %1;" : "=r"(r) : "f"(x)); return r;
}

__device__ __forceinline__ void mma_tf32(float* d, const uint32_t* a, const uint32_t* b) {
    asm volatile(
        "mma.sync.aligned.m16n8k8.row.col.f32.tf32.tf32.f32 "
        "{%0,%1,%2,%3}, {%4,%5,%6,%7}, {%8,%9}, {%0,%1,%2,%3};\n"
        : "+f"(d[0]), "+f"(d[1]), "+f"(d[2]), "+f"(d[3])
        : "r"(a[0]), "r"(a[1]), "r"(a[2]), "r"(a[3]), "r"(b[0]), "r"(b[1]));
}

template<int BN, bool EPI_RELU>
__global__ __launch_bounds__(256) void gemm_tc_kernel(
    const float* __restrict__ A, const float* __restrict__ W,
    const float* __restrict__ bias, const float* __restrict__ rowscale,
    float* __restrict__ C, int M)
{
    extern __shared__ uint32_t smem_u[];
    uint32_t* As = smem_u;                    // [128][AS_STRIDE]
    uint32_t* Bs = smem_u + 128 * AS_STRIDE;  // [128][BS_STRIDE]

    const int t    = threadIdx.x;
    const int lane = t & 31;
    const int wid  = t >> 5;
    const int m0   = blockIdx.x * 128;
    const int g    = lane >> 2;
    const int tt   = lane & 3;

    // warp tiling: 4 warps along M (32 rows each), 2 along N
    const int wm = wid & 3;
    const int wn = wid >> 2;
    constexpr int NT = BN / 16;     // n8 tiles per warp: 8 (BN=128) or 4 (BN=64)

    // ---- stage W (K=128 rows x BN cols) into Bs[k][n] ----
    for (int i = t; i < 128 * (BN / 4); i += 256) {
        int k  = i / (BN / 4);
        int c4 = i % (BN / 4);
        float4 v = __ldg(&((const float4*)W)[(size_t)k * (BN / 4) + c4]);
        uint32_t* p = &Bs[k * BS_STRIDE + 4 * c4];
        p[0] = f2tf(v.x); p[1] = f2tf(v.y); p[2] = f2tf(v.z); p[3] = f2tf(v.w);
    }
    // ---- stage A tile (128 rows x 128 cols) into As[m][k] ----
    for (int i = t; i < 4096; i += 256) {
        int r  = i >> 5;
        int c4 = i & 31;
        int gm = m0 + r;
        float4 v = make_float4(0.f, 0.f, 0.f, 0.f);
        if (gm < M) v = __ldg(&((const float4*)A)[(size_t)gm * 32 + c4]);
        uint32_t* p = &As[r * AS_STRIDE + 4 * c4];
        p[0] = f2tf(v.x); p[1] = f2tf(v.y); p[2] = f2tf(v.z); p[3] = f2tf(v.w);
    }
    __syncthreads();

    float acc[2][NT][4];
#pragma unroll
    for (int i = 0; i < 2; i++)
#pragma unroll
        for (int j = 0; j < NT; j++)
#pragma unroll
            for (int c = 0; c < 4; c++) acc[i][j][c] = 0.f;

#pragma unroll
    for (int k0 = 0; k0 < 128; k0 += 8) {
        uint32_t bf[NT][2];
#pragma unroll
        for (int j = 0; j < NT; j++) {
            int n = wn * (NT * 8) + j * 8 + g;
            bf[j][0] = Bs[(k0 + tt) * BS_STRIDE + n];
            bf[j][1] = Bs[(k0 + tt + 4) * BS_STRIDE + n];
        }
#pragma unroll
        for (int i = 0; i < 2; i++) {
            int m = wm * 32 + i * 16;
            uint32_t af[4];
            af[0] = As[(m + g)     * AS_STRIDE + k0 + tt];
            af[1] = As[(m + g + 8) * AS_STRIDE + k0 + tt];
            af[2] = As[(m + g)     * AS_STRIDE + k0 + tt + 4];
            af[3] = As[(m + g + 8) * AS_STRIDE + k0 + tt + 4];
#pragma unroll
            for (int j = 0; j < NT; j++) mma_tf32(acc[i][j], af, bf[j]);
        }
    }

    // ---- epilogue ----
#pragma unroll
    for (int i = 0; i < 2; i++) {
        int m_lo = m0 + wm * 32 + i * 16 + g;
        int m_hi = m_lo + 8;
        float rs_lo = 1.f, rs_hi = 1.f;
        if (EPI_RELU) {
            if (m_lo < M) rs_lo = __ldg(&rowscale[m_lo]);
            if (m_hi < M) rs_hi = __ldg(&rowscale[m_hi]);
        }
#pragma unroll
        for (int j = 0; j < NT; j++) {
            int n = wn * (NT * 8) + j * 8 + 2 * tt;
            float v0 = acc[i][j][0], v1 = acc[i][j][1];
            float v2 = acc[i][j][2], v3 = acc[i][j][3];
            if (EPI_RELU) {
                float b0 = __ldg(&bias[n]), b1 = __ldg(&bias[n + 1]);
                v0 = fmaxf(v0 + b0, 0.f) * rs_lo;
                v1 = fmaxf(v1 + b1, 0.f) * rs_lo;
                v2 = fmaxf(v2 + b0, 0.f) * rs_hi;
                v3 = fmaxf(v3 + b1, 0.f) * rs_hi;
            }
            if (m_lo < M) *(float2*)&C[(size_t)m_lo * BN + n] = make_float2(v0, v1);
            if (m_hi < M) *(float2*)&C[(size_t)m_hi * BN + n] = make_float2(v2, v3);
        }
    }
}

// ---------------- final: out = log_softmax(m3 + b3) over 64 cols ----------------
__global__ __launch_bounds__(256) void final_kernel(
    const float* __restrict__ m, const float* __restrict__ b3,
    float* __restrict__ out, int n)
{
    int row = (blockIdx.x * 256 + threadIdx.x) >> 5;
    int lane = threadIdx.x & 31;
    if (row >= n) return;
    float2 v = *(const float2*)&m[(size_t)row * 64 + lane * 2];
    float2 bb = *(const float2*)&b3[lane * 2];
    v.x += bb.x; v.y += bb.y;
    float mx = fmaxf(v.x, v.y);
#pragma unroll
    for (int o = 16; o > 0; o >>= 1) mx = fmaxf(mx, __shfl_xor_sync(0xFFFFFFFFu, mx, o));
    float e = __expf(v.x - mx) + __expf(v.y - mx);
#pragma unroll
    for (int o = 16; o > 0; o >>= 1) e += __shfl_xor_sync(0xFFFFFFFFu, e, o);
    float lse = logf(e) + mx;
    float2 r; r.x = v.x - lse; r.y = v.y - lse;
    *(float2*)&out[(size_t)row * 64 + lane * 2] = r;
}

// ---------------- launch ----------------
extern "C" void kernel_launch(void* const* d_in, const int* in_sizes, int n_in,
                              void* d_out, int out_size)
{
    const float* features = (const float*)d_in[0];
    const int*   src      = (const int*)  d_in[1];
    const int*   dst      = (const int*)  d_in[2];
    const float* W1       = (const float*)d_in[3];
    const float* b1       = (const float*)d_in[4];
    const float* W2       = (const float*)d_in[5];
    const float* b2       = (const float*)d_in[6];
    const float* W3       = (const float*)d_in[7];
    const float* b3       = (const float*)d_in[8];
    float* out = (float*)d_out;

    const int N = in_sizes[0] / DIN;   // 100000
    const int E = in_sizes[1];         // 1600000

    float* bufA; cudaGetSymbolAddress((void**)&bufA, g_bufA);
    float* bufB; cudaGetSymbolAddress((void**)&bufB, g_bufB);
    float* bufG; cudaGetSymbolAddress((void**)&bufG, g_bufG);
    float* nsrc; cudaGetSymbolAddress((void**)&nsrc, g_norm_src);

    // allow >48KB dynamic smem for the tensor-core GEMMs (idempotent)
    static bool attr_done = false;
    if (!attr_done) {
        cudaFuncSetAttribute((const void*)gemm_tc_kernel<128, true>,
                             cudaFuncAttributeMaxDynamicSharedMemorySize, GEMM_SMEM_BYTES);
        cudaFuncSetAttribute((const void*)gemm_tc_kernel<64, false>,
                             cudaFuncAttributeMaxDynamicSharedMemorySize, GEMM_SMEM_BYTES);
        attr_done = true;
    }

    // ---- CSR build (per launch; graph-capturable, deterministic up to atomic order) ----
    zero_deg_kernel<<<(N + 255) / 256, 256>>>(N);
    deg_kernel<<<(E + 255) / 256, 256>>>(src, dst, E);
    norm_kernel<<<(N + 255) / 256, 256>>>(N);
    int nblk = (N + 1023) / 1024;
    scan1_kernel<<<nblk, 256>>>(N);
    scan2_kernel<<<1, 128>>>(nblk);
    scan3_kernel<<<(N + 1 + 255) / 256, 256>>>(N, E);
    scatter_kernel<<<(E + 255) / 256, 256>>>(src, dst, E);

    const int spmm_blocks = (N * 32 + 255) / 256;   // warp per node
    const int gemm_blocks = (N + 127) / 128;

    // ---- layer 1: aggregate(features * ns) * nd -> A ; B = relu(A@W1+b1)*ns ----
    spmm_kernel<128, true ><<<spmm_blocks, 256>>>(features, nsrc, bufA, N);
    gemm_tc_kernel<128, true ><<<gemm_blocks, 256, GEMM_SMEM_BYTES>>>(bufA, W1, b1, nsrc, bufB, N);

    // ---- layer 2: aggregate(B) * nd -> A ; B = relu(A@W2+b2)*ns ----
    spmm_kernel<128, false><<<spmm_blocks, 256>>>(bufB, nullptr, bufA, N);
    gemm_tc_kernel<128, true ><<<gemm_blocks, 256, GEMM_SMEM_BYTES>>>(bufA, W2, b2, nsrc, bufB, N);

    // ---- layer 3 (W-first): G = B@W3 ; A[:, :64] = aggregate(G) * nd ; out = log_softmax(A + b3) ----
    gemm_tc_kernel<64, false><<<gemm_blocks, 256, GEMM_SMEM_BYTES>>>(bufB, W3, nullptr, nullptr, bufG, N);
    spmm_kernel<64, false><<<spmm_blocks, 256>>>(bufG, nullptr, bufA, N);
    final_kernel<<<(N * 32 + 255) / 256, 256>>>(bufA, b3, out, N);
}

// round 3
// speedup vs baseline: 1.7737x; 1.7737x over previous
#include <cuda_runtime.h>
#include <cuda_bf16.h>
#include <math.h>
#include <stdint.h>

// Problem constants (fixed by the dataset)
#define NNODES 100000
#define NEDGES 1600000
#define DIN 128
#define DH  128
#define DOUT 64

// ---------------- device scratch (no allocations; zero-init at module load) ----------------
// node-feature matrices stored as bf16 pairs (uint32 = 2 x bf16)
__device__ __align__(16) static uint32_t g_featbf[(size_t)NNODES * 64]; // features bf16
__device__ __align__(16) static uint32_t g_aggA[(size_t)NNODES * 64];   // aggregate buffer
__device__ __align__(16) static uint32_t g_h[(size_t)NNODES * 64];      // layer output
__device__ __align__(16) static uint32_t g_G[(size_t)NNODES * 32];      // h2 @ W3 (64 cols)
__device__ static int   g_rowptr[NNODES + 1];
__device__ static int   g_cursor[NNODES + 1];
__device__ static int   g_colidx[NEDGES];
__device__ static int   g_outdeg[NNODES];                               // re-zeroed by scatter
__device__ static int   g_indeg[NNODES];                                // re-zeroed by scatter
__device__ static float g_norm_src[NNODES];
__device__ static float g_norm_dst[NNODES];
__device__ static volatile unsigned long long g_state[128];             // lookback state, re-zeroed by scatter

// ---------------- helpers ----------------
__device__ __forceinline__ uint32_t pack_bf16(float lo, float hi) {
    uint32_t r; asm("cvt.rn.bf16x2.f32 %0, %1, %2;" : "=r"(r) : "f"(hi), "f"(lo)); return r;
}
__device__ __forceinline__ float2 unpack_bf16(uint32_t u) {
    __nv_bfloat162 b = *reinterpret_cast<__nv_bfloat162*>(&u);
    return __bfloat1622float2(b);   // .x = low half
}

// ---------------- kernel 1: degree histogram + feature fp32->bf16 convert ----------------
__global__ __launch_bounds__(256) void deg_convert_kernel(
    const int* __restrict__ src, const int* __restrict__ dst,
    const float4* __restrict__ feat4, int E, int nconv)
{
    int e = blockIdx.x * 256 + threadIdx.x;
    if (e < E) {
        atomicAdd(&g_outdeg[src[e]], 1);
        atomicAdd(&g_indeg[dst[e]], 1);
    }
    if (e < nconv) {   // nconv = N*16 uint4s (8 floats each)
        float4 f0 = __ldg(&feat4[(size_t)e * 2]);
        float4 f1 = __ldg(&feat4[(size_t)e * 2 + 1]);
        uint4 o;
        o.x = pack_bf16(f0.x, f0.y); o.y = pack_bf16(f0.z, f0.w);
        o.z = pack_bf16(f1.x, f1.y); o.w = pack_bf16(f1.z, f1.w);
        ((uint4*)g_featbf)[e] = o;
    }
}

// ---------------- kernel 2: single-pass scan (decoupled lookback) + norms ----------------
// grid = ceil(N/1024) = 98 blocks (< 148 SMs -> all co-resident, no deadlock)
__global__ __launch_bounds__(256) void scan_kernel(int n, int E)
{
    __shared__ int warp_sums[8];
    __shared__ int s_prefix;
    int b = blockIdx.x, t = threadIdx.x;
    int lane = t & 31, wid = t >> 5;
    int idx0 = b * 1024 + t * 4;

    int v[4];
#pragma unroll
    for (int i = 0; i < 4; i++) { int idx = idx0 + i; v[i] = (idx < n) ? g_indeg[idx] : 0; }
    int s = v[0] + v[1] + v[2] + v[3];
    int ss = s;
#pragma unroll
    for (int o = 1; o < 32; o <<= 1) { int x = __shfl_up_sync(0xFFFFFFFFu, ss, o); if (lane >= o) ss += x; }
    if (lane == 31) warp_sums[wid] = ss;
    __syncthreads();
    if (wid == 0) {
        int w = (lane < 8) ? warp_sums[lane] : 0;
#pragma unroll
        for (int o = 1; o < 8; o <<= 1) { int x = __shfl_up_sync(0xFFFFFFFFu, w, o); if (lane >= o) w += x; }
        if (lane < 8) warp_sums[lane] = w;
    }
    __syncthreads();
    int T = warp_sums[7];
    int excl_in_block = ss - s + ((wid > 0) ? warp_sums[wid - 1] : 0);

    // publish own aggregate (block 0 publishes final prefix immediately)
    if (t == 0) {
        unsigned long long pk = ((unsigned long long)(unsigned)T << 2) | (b == 0 ? 2u : 1u);
        g_state[b] = pk;
        __threadfence();
    }
    // warp 0 performs the lookback
    if (wid == 0) {
        int running = 0;
        if (b > 0) {
            int look = b - 1 - lane;
            while (true) {
                unsigned long long sv = (look >= 0) ? g_state[look] : 2ULL; // past-begin = PREFIX 0
                unsigned flag = (unsigned)(sv & 3ULL);
                int val = (int)(sv >> 2);
                unsigned inv = __ballot_sync(0xFFFFFFFFu, flag == 0u);
                if (inv) continue;
                unsigned pref = __ballot_sync(0xFFFFFFFFu, flag == 2u);
                if (pref) {
                    int fp = __ffs(pref) - 1;           // nearest PREFIX (lane 0 = b-1)
                    int contrib = (lane <= fp) ? val : 0;
#pragma unroll
                    for (int o = 16; o > 0; o >>= 1) contrib += __shfl_xor_sync(0xFFFFFFFFu, contrib, o);
                    running += contrib;
                    break;
                } else {
                    int contrib = val;
#pragma unroll
                    for (int o = 16; o > 0; o >>= 1) contrib += __shfl_xor_sync(0xFFFFFFFFu, contrib, o);
                    running += contrib;
                    look -= 32;
                }
            }
        }
        if (t == 0) {
            s_prefix = running;
            if (b > 0) {
                unsigned long long pk = ((unsigned long long)(unsigned)(running + T) << 2) | 2u;
                g_state[b] = pk;
                __threadfence();
            }
        }
    }
    __syncthreads();

    int run = s_prefix + excl_in_block;
#pragma unroll
    for (int i = 0; i < 4; i++) {
        int idx = idx0 + i;
        if (idx < n) {
            g_rowptr[idx] = run;
            g_cursor[idx] = run;
            int od = g_outdeg[idx]; if (od < 1) od = 1;
            int id = v[i];          if (id < 1) id = 1;
            g_norm_src[idx] = rsqrtf((float)od);
            g_norm_dst[idx] = rsqrtf((float)id);
        }
        run += v[i];
    }
    if (b == 0 && t == 0) g_rowptr[n] = E;
}

// ---------------- kernel 3: CSR scatter (+ re-zero degs/state for next invocation) ----------------
__global__ __launch_bounds__(256) void scatter_kernel(
    const int* __restrict__ src, const int* __restrict__ dst, int E, int n)
{
    int e = blockIdx.x * 256 + threadIdx.x;
    if (e < E) {
        int d = dst[e];
        int p = atomicAdd(&g_cursor[d], 1);
        g_colidx[p] = src[e];
    }
    if (e < n) { g_outdeg[e] = 0; g_indeg[e] = 0; }   // degs consumed by scan; reset for next call
    if (e < 128) g_state[e] = 0ULL;                   // lookback state reset for next call
}

// ---------------- SpMM (bf16 in, bf16 out): out[v] = nd[v] * sum (s(u) * x[u]) ----------------
template<bool SRCSCALE>
__global__ __launch_bounds__(256) void spmm_bf16_kernel(
    const uint2* __restrict__ x, const float* __restrict__ sscale,
    uint2* __restrict__ out, int n)
{
    int warp = (blockIdx.x * 256 + threadIdx.x) >> 5;
    int lane = threadIdx.x & 31;
    if (warp >= n) return;
    int beg = __ldg(&g_rowptr[warp]);
    int end = __ldg(&g_rowptr[warp + 1]);
    float dsc = __ldg(&g_norm_dst[warp]);

    float a0 = 0.f, a1 = 0.f, a2 = 0.f, a3 = 0.f;
    float c0 = 0.f, c1 = 0.f, c2 = 0.f, c3 = 0.f;
    int e = beg;
    for (; e + 1 < end; e += 2) {
        int u0 = __ldg(&g_colidx[e]);
        int u1 = __ldg(&g_colidx[e + 1]);
        float s0 = SRCSCALE ? __ldg(&sscale[u0]) : 1.0f;
        float s1 = SRCSCALE ? __ldg(&sscale[u1]) : 1.0f;
        uint2 v0 = __ldg(&x[(size_t)u0 * 32 + lane]);
        uint2 v1 = __ldg(&x[(size_t)u1 * 32 + lane]);
        float2 p = unpack_bf16(v0.x), q = unpack_bf16(v0.y);
        a0 += s0 * p.x; a1 += s0 * p.y; a2 += s0 * q.x; a3 += s0 * q.y;
        p = unpack_bf16(v1.x); q = unpack_bf16(v1.y);
        c0 += s1 * p.x; c1 += s1 * p.y; c2 += s1 * q.x; c3 += s1 * q.y;
    }
    if (e < end) {
        int u0 = __ldg(&g_colidx[e]);
        float s0 = SRCSCALE ? __ldg(&sscale[u0]) : 1.0f;
        uint2 v0 = __ldg(&x[(size_t)u0 * 32 + lane]);
        float2 p = unpack_bf16(v0.x), q = unpack_bf16(v0.y);
        a0 += s0 * p.x; a1 += s0 * p.y; a2 += s0 * q.x; a3 += s0 * q.y;
    }
    a0 = (a0 + c0) * dsc; a1 = (a1 + c1) * dsc;
    a2 = (a2 + c2) * dsc; a3 = (a3 + c3) * dsc;
    uint2 r; r.x = pack_bf16(a0, a1); r.y = pack_bf16(a2, a3);
    out[(size_t)warp * 32 + lane] = r;
}

// ---------------- SpMM over G (64 cols) fused with +b3 and log_softmax ----------------
__global__ __launch_bounds__(256) void spmm_final_kernel(
    const uint32_t* __restrict__ G, const float* __restrict__ b3,
    float* __restrict__ out, int n)
{
    int warp = (blockIdx.x * 256 + threadIdx.x) >> 5;
    int lane = threadIdx.x & 31;
    if (warp >= n) return;
    int beg = __ldg(&g_rowptr[warp]);
    int end = __ldg(&g_rowptr[warp + 1]);
    float dsc = __ldg(&g_norm_dst[warp]);

    float a0 = 0.f, a1 = 0.f, c0 = 0.f, c1 = 0.f;
    int e = beg;
    for (; e + 1 < end; e += 2) {
        int u0 = __ldg(&g_colidx[e]);
        int u1 = __ldg(&g_colidx[e + 1]);
        float2 p = unpack_bf16(__ldg(&G[(size_t)u0 * 32 + lane]));
        float2 q = unpack_bf16(__ldg(&G[(size_t)u1 * 32 + lane]));
        a0 += p.x; a1 += p.y; c0 += q.x; c1 += q.y;
    }
    if (e < end) {
        int u0 = __ldg(&g_colidx[e]);
        float2 p = unpack_bf16(__ldg(&G[(size_t)u0 * 32 + lane]));
        a0 += p.x; a1 += p.y;
    }
    float2 bb = __ldg(&((const float2*)b3)[lane]);
    float r0 = (a0 + c0) * dsc + bb.x;
    float r1 = (a1 + c1) * dsc + bb.y;
    float mx = fmaxf(r0, r1);
#pragma unroll
    for (int o = 16; o > 0; o >>= 1) mx = fmaxf(mx, __shfl_xor_sync(0xFFFFFFFFu, mx, o));
    float es = __expf(r0 - mx) + __expf(r1 - mx);
#pragma unroll
    for (int o = 16; o > 0; o >>= 1) es += __shfl_xor_sync(0xFFFFFFFFu, es, o);
    float lse = logf(es) + mx;
    ((float2*)out)[(size_t)warp * 32 + lane] = make_float2(r0 - lse, r1 - lse);
}

// ---------------- bf16 tensor-core GEMM ----------------
// C[M x BN](bf16) = A[M x 128](bf16) @ W[128 x BN](fp32->bf16); EPI: relu(acc+bias)*rowscale
// smem (uint32 = bf16x2): As[128][68] m-major k-pairs (68%32=4 -> frag bank 4g+t, conflict-free)
//                          Bs[64][BN+8] kpair-major    (stride%32=8 -> frag bank 8t+g, conflict-free)
#define AS_STRIDE 68
__device__ __forceinline__ void mma_bf16(float* d, const uint32_t* a, const uint32_t* b) {
    asm volatile(
        "mma.sync.aligned.m16n8k16.row.col.f32.bf16.bf16.f32 "
        "{%0,%1,%2,%3}, {%4,%5,%6,%7}, {%8,%9}, {%0,%1,%2,%3};\n"
        : "+f"(d[0]), "+f"(d[1]), "+f"(d[2]), "+f"(d[3])
        : "r"(a[0]), "r"(a[1]), "r"(a[2]), "r"(a[3]), "r"(b[0]), "r"(b[1]));
}

template<int BN, bool EPI>
__global__ __launch_bounds__(256) void gemm_bf16_kernel(
    const uint32_t* __restrict__ A,   // bf16 pairs, row stride 64
    const float* __restrict__ W,      // fp32 [128][BN]
    const float* __restrict__ bias, const float* __restrict__ rowscale,
    uint32_t* __restrict__ C,         // bf16 pairs, row stride BN/2
    int M)
{
    constexpr int BSS = BN + 8;
    extern __shared__ uint32_t smem_u[];
    uint32_t* As = smem_u;                    // [128][AS_STRIDE]
    uint32_t* Bs = smem_u + 128 * AS_STRIDE;  // [64][BSS]

    const int t    = threadIdx.x;
    const int lane = t & 31;
    const int wid  = t >> 5;
    const int m0   = blockIdx.x * 128;
    const int g    = lane >> 2;
    const int tt   = lane & 3;
    const int wm   = wid & 3;
    const int wn   = wid >> 2;
    constexpr int NT = BN / 16;

    // stage W: Bs[kk][n] = {W[2kk][n], W[2kk+1][n]}
    for (int i = t; i < 64 * (BN / 4); i += 256) {
        int kk = i / (BN / 4);
        int n4 = (i % (BN / 4)) * 4;
        float4 r0 = __ldg((const float4*)&W[(size_t)(2 * kk) * BN + n4]);
        float4 r1 = __ldg((const float4*)&W[(size_t)(2 * kk + 1) * BN + n4]);
        uint4 o;
        o.x = pack_bf16(r0.x, r1.x); o.y = pack_bf16(r0.y, r1.y);
        o.z = pack_bf16(r0.z, r1.z); o.w = pack_bf16(r0.w, r1.w);
        *(uint4*)&Bs[kk * BSS + n4] = o;
    }
    // stage A: As[m][kk] = A row pairs (direct copy, already bf16)
    for (int i = t; i < 128 * 16; i += 256) {
        int r = i >> 4;
        int q = i & 15;
        int gm = m0 + r;
        uint4 v = make_uint4(0u, 0u, 0u, 0u);
        if (gm < M) v = __ldg(&((const uint4*)A)[(size_t)gm * 16 + q]);
        *(uint4*)&As[r * AS_STRIDE + q * 4] = v;
    }
    __syncthreads();

    float acc[2][NT][4];
#pragma unroll
    for (int i = 0; i < 2; i++)
#pragma unroll
        for (int j = 0; j < NT; j++)
#pragma unroll
            for (int c = 0; c < 4; c++) acc[i][j][c] = 0.f;

#pragma unroll
    for (int ks = 0; ks < 8; ks++) {
        int kb = ks * 8;
        uint32_t bf[NT][2];
#pragma unroll
        for (int j = 0; j < NT; j++) {
            int n = wn * (NT * 8) + j * 8 + g;
            bf[j][0] = Bs[(kb + tt) * BSS + n];
            bf[j][1] = Bs[(kb + tt + 4) * BSS + n];
        }
#pragma unroll
        for (int i = 0; i < 2; i++) {
            int m = wm * 32 + i * 16;
            uint32_t af[4];
            af[0] = As[(m + g)     * AS_STRIDE + kb + tt];
            af[1] = As[(m + g + 8) * AS_STRIDE + kb + tt];
            af[2] = As[(m + g)     * AS_STRIDE + kb + tt + 4];
            af[3] = As[(m + g + 8) * AS_STRIDE + kb + tt + 4];
#pragma unroll
            for (int j = 0; j < NT; j++) mma_bf16(acc[i][j], af, bf[j]);
        }
    }

    // epilogue: pack fp32 accum -> bf16 pairs
#pragma unroll
    for (int i = 0; i < 2; i++) {
        int m_lo = m0 + wm * 32 + i * 16 + g;
        int m_hi = m_lo + 8;
        float rs_lo = 1.f, rs_hi = 1.f;
        if (EPI) {
            if (m_lo < M) rs_lo = __ldg(&rowscale[m_lo]);
            if (m_hi < M) rs_hi = __ldg(&rowscale[m_hi]);
        }
#pragma unroll
        for (int j = 0; j < NT; j++) {
            int n = wn * (NT * 8) + j * 8 + 2 * tt;
            float v0 = acc[i][j][0], v1 = acc[i][j][1];
            float v2 = acc[i][j][2], v3 = acc[i][j][3];
            if (EPI) {
                float b0 = __ldg(&bias[n]), b1 = __ldg(&bias[n + 1]);
                v0 = fmaxf(v0 + b0, 0.f) * rs_lo;
                v1 = fmaxf(v1 + b1, 0.f) * rs_lo;
                v2 = fmaxf(v2 + b0, 0.f) * rs_hi;
                v3 = fmaxf(v3 + b1, 0.f) * rs_hi;
            }
            if (m_lo < M) C[(size_t)m_lo * (BN / 2) + (n >> 1)] = pack_bf16(v0, v1);
            if (m_hi < M) C[(size_t)m_hi * (BN / 2) + (n >> 1)] = pack_bf16(v2, v3);
        }
    }
}

#define GEMM128_SMEM ((128 * AS_STRIDE + 64 * (128 + 8)) * 4)
#define GEMM64_SMEM  ((128 * AS_STRIDE + 64 * (64 + 8)) * 4)

// ---------------- launch ----------------
extern "C" void kernel_launch(void* const* d_in, const int* in_sizes, int n_in,
                              void* d_out, int out_size)
{
    const float* features = (const float*)d_in[0];
    const int*   src      = (const int*)  d_in[1];
    const int*   dst      = (const int*)  d_in[2];
    const float* W1       = (const float*)d_in[3];
    const float* b1       = (const float*)d_in[4];
    const float* W2       = (const float*)d_in[5];
    const float* b2       = (const float*)d_in[6];
    const float* W3       = (const float*)d_in[7];
    const float* b3       = (const float*)d_in[8];
    float* out = (float*)d_out;

    const int N = in_sizes[0] / DIN;   // 100000
    const int E = in_sizes[1];         // 1600000

    uint32_t* featbf; cudaGetSymbolAddress((void**)&featbf, g_featbf);
    uint32_t* aggA;   cudaGetSymbolAddress((void**)&aggA,   g_aggA);
    uint32_t* hbuf;   cudaGetSymbolAddress((void**)&hbuf,   g_h);
    uint32_t* Gbuf;   cudaGetSymbolAddress((void**)&Gbuf,   g_G);
    float*    nsrc;   cudaGetSymbolAddress((void**)&nsrc,   g_norm_src);

    static bool attr_done = false;
    if (!attr_done) {
        cudaFuncSetAttribute((const void*)gemm_bf16_kernel<128, true>,
                             cudaFuncAttributeMaxDynamicSharedMemorySize, GEMM128_SMEM);
        cudaFuncSetAttribute((const void*)gemm_bf16_kernel<64, false>,
                             cudaFuncAttributeMaxDynamicSharedMemorySize, GEMM64_SMEM);
        attr_done = true;
    }

    const int nconv = N * 16;                       // uint4s of bf16 features
    const int degcv_blocks = ((E > nconv ? E : nconv) + 255) / 256;
    const int scan_blocks  = (N + 1023) / 1024;     // 98 < 148 SMs (lookback safety)
    const int spmm_blocks  = (N * 32 + 255) / 256;  // warp per node
    const int gemm_blocks  = (N + 127) / 128;

    // ---- CSR build: exactly 3 kernels so spmm1 is the 4th launch (ncu slot) ----
    deg_convert_kernel<<<degcv_blocks, 256>>>(src, dst, (const float4*)features, E, nconv);
    scan_kernel<<<scan_blocks, 256>>>(N, E);
    scatter_kernel<<<(E + 255) / 256, 256>>>(src, dst, E, N);

    // ---- layer 1 ----
    spmm_bf16_kernel<true ><<<spmm_blocks, 256>>>((const uint2*)featbf, nsrc, (uint2*)aggA, N);
    gemm_bf16_kernel<128, true ><<<gemm_blocks, 256, GEMM128_SMEM>>>(aggA, W1, b1, nsrc, hbuf, N);

    // ---- layer 2 ----
    spmm_bf16_kernel<false><<<spmm_blocks, 256>>>((const uint2*)hbuf, nullptr, (uint2*)aggA, N);
    gemm_bf16_kernel<128, true ><<<gemm_blocks, 256, GEMM128_SMEM>>>(aggA, W2, b2, nsrc, hbuf, N);

    // ---- layer 3 (W-first) + fused log_softmax ----
    gemm_bf16_kernel<64, false><<<gemm_blocks, 256, GEMM64_SMEM>>>(hbuf, W3, nullptr, nullptr, Gbuf, N);
    spmm_final_kernel<<<spmm_blocks, 256>>>(Gbuf, b3, out, N);
}

// round 4
// speedup vs baseline: 1.8612x; 1.0493x over previous
#include <cuda_runtime.h>
#include <cuda_bf16.h>
#include <math.h>
#include <stdint.h>

// Problem constants (fixed by the dataset)
#define NNODES 100000
#define NEDGES 1600000
#define DIN 128
#define DH  128
#define DOUT 64

// ---------------- device scratch (no allocations; zero-init at module load) ----------------
__device__ __align__(16) static uint32_t g_featbf[(size_t)NNODES * 64]; // features*norm_src, bf16 pairs
__device__ __align__(16) static uint32_t g_aggA[(size_t)NNODES * 64];   // aggregate buffer
__device__ __align__(16) static uint32_t g_h[(size_t)NNODES * 64];      // layer output
__device__ __align__(16) static uint32_t g_G[(size_t)NNODES * 32];      // h2 @ W3 (64 cols)
__device__ static int   g_rowptr[NNODES + 1];
__device__ static int   g_cursor[NNODES + 1];
__device__ static int   g_colidx[NEDGES];
__device__ static int   g_outdeg[NNODES];                               // re-zeroed by scatter
__device__ static int   g_indeg[NNODES];                                // re-zeroed by scatter
__device__ static float g_norm_src[NNODES];
__device__ static float g_norm_dst[NNODES];
__device__ static volatile unsigned long long g_state[128];             // lookback state, re-zeroed by scatter

// ---------------- helpers ----------------
__device__ __forceinline__ uint32_t pack_bf16(float lo, float hi) {
    uint32_t r; asm("cvt.rn.bf16x2.f32 %0, %1, %2;" : "=r"(r) : "f"(hi), "f"(lo)); return r;
}
// accumulate a bf16x2 word into an f32x2 accumulator: SHL + LOP3 + ADD2 (exact)
__device__ __forceinline__ void acc_bf16x2(unsigned long long& acc, uint32_t w) {
    unsigned long long val;
    asm("{\n\t.reg .b32 lo, hi;\n\t"
        "shl.b32 lo, %1, 16;\n\t"
        "and.b32 hi, %1, 0xFFFF0000;\n\t"
        "mov.b64 %0, {lo, hi};\n\t}"
        : "=l"(val) : "r"(w));
    asm("add.rn.f32x2 %0, %0, %1;" : "+l"(acc) : "l"(val));
}
__device__ __forceinline__ void add_f32x2(unsigned long long& a, unsigned long long b) {
    asm("add.rn.f32x2 %0, %0, %1;" : "+l"(a) : "l"(b));
}
__device__ __forceinline__ float2 unpack_f32x2(unsigned long long a) {
    uint32_t lo, hi;
    asm("mov.b64 {%0, %1}, %2;" : "=r"(lo), "=r"(hi) : "l"(a));
    return make_float2(__uint_as_float(lo), __uint_as_float(hi));
}
__device__ __forceinline__ float2 unpack_bf16(uint32_t u) {
    __nv_bfloat162 b = *reinterpret_cast<__nv_bfloat162*>(&u);
    return __bfloat1622float2(b);
}

// ---------------- kernel 1: degree histogram ----------------
__global__ __launch_bounds__(256) void deg_kernel(
    const int* __restrict__ src, const int* __restrict__ dst, int E)
{
    int e = blockIdx.x * 256 + threadIdx.x;
    if (e < E) {
        atomicAdd(&g_outdeg[src[e]], 1);
        atomicAdd(&g_indeg[dst[e]], 1);
    }
}

// ---------------- kernel 2: single-pass scan (decoupled lookback) + norms ----------------
// grid = ceil(N/1024) = 98 blocks (< 148 SMs -> all co-resident, no deadlock)
__global__ __launch_bounds__(256) void scan_kernel(int n, int E)
{
    __shared__ int warp_sums[8];
    __shared__ int s_prefix;
    int b = blockIdx.x, t = threadIdx.x;
    int lane = t & 31, wid = t >> 5;
    int idx0 = b * 1024 + t * 4;

    int v[4];
#pragma unroll
    for (int i = 0; i < 4; i++) { int idx = idx0 + i; v[i] = (idx < n) ? g_indeg[idx] : 0; }
    int s = v[0] + v[1] + v[2] + v[3];
    int ss = s;
#pragma unroll
    for (int o = 1; o < 32; o <<= 1) { int x = __shfl_up_sync(0xFFFFFFFFu, ss, o); if (lane >= o) ss += x; }
    if (lane == 31) warp_sums[wid] = ss;
    __syncthreads();
    if (wid == 0) {
        int w = (lane < 8) ? warp_sums[lane] : 0;
#pragma unroll
        for (int o = 1; o < 8; o <<= 1) { int x = __shfl_up_sync(0xFFFFFFFFu, w, o); if (lane >= o) w += x; }
        if (lane < 8) warp_sums[lane] = w;
    }
    __syncthreads();
    int T = warp_sums[7];
    int excl_in_block = ss - s + ((wid > 0) ? warp_sums[wid - 1] : 0);

    if (t == 0) {
        unsigned long long pk = ((unsigned long long)(unsigned)T << 2) | (b == 0 ? 2u : 1u);
        g_state[b] = pk;
        __threadfence();
    }
    if (wid == 0) {
        int running = 0;
        if (b > 0) {
            int look = b - 1 - lane;
            while (true) {
                unsigned long long sv = (look >= 0) ? g_state[look] : 2ULL;
                unsigned flag = (unsigned)(sv & 3ULL);
                int val = (int)(sv >> 2);
                unsigned inv = __ballot_sync(0xFFFFFFFFu, flag == 0u);
                if (inv) continue;
                unsigned pref = __ballot_sync(0xFFFFFFFFu, flag == 2u);
                if (pref) {
                    int fp = __ffs(pref) - 1;
                    int contrib = (lane <= fp) ? val : 0;
#pragma unroll
                    for (int o = 16; o > 0; o >>= 1) contrib += __shfl_xor_sync(0xFFFFFFFFu, contrib, o);
                    running += contrib;
                    break;
                } else {
                    int contrib = val;
#pragma unroll
                    for (int o = 16; o > 0; o >>= 1) contrib += __shfl_xor_sync(0xFFFFFFFFu, contrib, o);
                    running += contrib;
                    look -= 32;
                }
            }
        }
        if (t == 0) {
            s_prefix = running;
            if (b > 0) {
                unsigned long long pk = ((unsigned long long)(unsigned)(running + T) << 2) | 2u;
                g_state[b] = pk;
                __threadfence();
            }
        }
    }
    __syncthreads();

    int run = s_prefix + excl_in_block;
#pragma unroll
    for (int i = 0; i < 4; i++) {
        int idx = idx0 + i;
        if (idx < n) {
            g_rowptr[idx] = run;
            g_cursor[idx] = run;
            int od = g_outdeg[idx]; if (od < 1) od = 1;
            int id = v[i];          if (id < 1) id = 1;
            g_norm_src[idx] = rsqrtf((float)od);
            g_norm_dst[idx] = rsqrtf((float)id);
        }
        run += v[i];
    }
    if (b == 0 && t == 0) g_rowptr[n] = E;
}

// ---------------- kernel 3: scatter + feature convert (fp32 * norm_src -> bf16) + state reset ----------------
__global__ __launch_bounds__(256) void scatter_convert_kernel(
    const int* __restrict__ src, const int* __restrict__ dst,
    const float4* __restrict__ feat4, int E, int n, int nconv)
{
    int e = blockIdx.x * 256 + threadIdx.x;
    if (e < E) {
        int d = dst[e];
        int p = atomicAdd(&g_cursor[d], 1);
        g_colidx[p] = src[e];
    }
    if (e < nconv) {   // nconv = N*16 uint4s (8 floats each)
        int node = e >> 4;
        float ns = __ldg(&g_norm_src[node]);
        float4 f0 = __ldg(&feat4[(size_t)e * 2]);
        float4 f1 = __ldg(&feat4[(size_t)e * 2 + 1]);
        uint4 o;
        o.x = pack_bf16(f0.x * ns, f0.y * ns); o.y = pack_bf16(f0.z * ns, f0.w * ns);
        o.z = pack_bf16(f1.x * ns, f1.y * ns); o.w = pack_bf16(f1.z * ns, f1.w * ns);
        ((uint4*)g_featbf)[e] = o;
    }
    if (e < n) { g_outdeg[e] = 0; g_indeg[e] = 0; }
    if (e < 128) g_state[e] = 0ULL;
}

// ---------------- SpMM 128-col, scale-free: out[v] = nd[v] * sum x[u] ----------------
__global__ __launch_bounds__(256) void spmm128_kernel(
    const uint2* __restrict__ x, uint2* __restrict__ out, int n)
{
    int warp = (blockIdx.x * 256 + threadIdx.x) >> 5;
    int lane = threadIdx.x & 31;
    if (warp >= n) return;
    int beg = __ldg(&g_rowptr[warp]);
    int end = __ldg(&g_rowptr[warp + 1]);
    float dsc = __ldg(&g_norm_dst[warp]);
    const uint2* xp = x + lane;

    unsigned long long a0 = 0ULL, a1 = 0ULL;   // chain A: f32x2 accum for word0/word1
    unsigned long long b0 = 0ULL, b1 = 0ULL;   // chain B
    int e = beg;
    for (; e + 3 < end; e += 4) {
        int u0 = __ldg(&g_colidx[e]);
        int u1 = __ldg(&g_colidx[e + 1]);
        int u2 = __ldg(&g_colidx[e + 2]);
        int u3 = __ldg(&g_colidx[e + 3]);
        uint2 v0 = __ldg(xp + (size_t)u0 * 32);
        uint2 v1 = __ldg(xp + (size_t)u1 * 32);
        uint2 v2 = __ldg(xp + (size_t)u2 * 32);
        uint2 v3 = __ldg(xp + (size_t)u3 * 32);
        acc_bf16x2(a0, v0.x); acc_bf16x2(a1, v0.y);
        acc_bf16x2(b0, v1.x); acc_bf16x2(b1, v1.y);
        acc_bf16x2(a0, v2.x); acc_bf16x2(a1, v2.y);
        acc_bf16x2(b0, v3.x); acc_bf16x2(b1, v3.y);
    }
    for (; e < end; e++) {
        int u0 = __ldg(&g_colidx[e]);
        uint2 v0 = __ldg(xp + (size_t)u0 * 32);
        acc_bf16x2(a0, v0.x); acc_bf16x2(a1, v0.y);
    }
    add_f32x2(a0, b0); add_f32x2(a1, b1);
    float2 f0 = unpack_f32x2(a0);
    float2 f1 = unpack_f32x2(a1);
    uint2 r;
    r.x = pack_bf16(f0.x * dsc, f0.y * dsc);
    r.y = pack_bf16(f1.x * dsc, f1.y * dsc);
    out[(size_t)warp * 32 + lane] = r;
}

// ---------------- SpMM over G (64 cols) fused with +b3 and log_softmax ----------------
__global__ __launch_bounds__(256) void spmm_final_kernel(
    const uint32_t* __restrict__ G, const float* __restrict__ b3,
    float* __restrict__ out, int n)
{
    int warp = (blockIdx.x * 256 + threadIdx.x) >> 5;
    int lane = threadIdx.x & 31;
    if (warp >= n) return;
    int beg = __ldg(&g_rowptr[warp]);
    int end = __ldg(&g_rowptr[warp + 1]);
    float dsc = __ldg(&g_norm_dst[warp]);
    const uint32_t* gp = G + lane;

    unsigned long long a0 = 0ULL, b0 = 0ULL;
    int e = beg;
    for (; e + 3 < end; e += 4) {
        int u0 = __ldg(&g_colidx[e]);
        int u1 = __ldg(&g_colidx[e + 1]);
        int u2 = __ldg(&g_colidx[e + 2]);
        int u3 = __ldg(&g_colidx[e + 3]);
        uint32_t v0 = __ldg(gp + (size_t)u0 * 32);
        uint32_t v1 = __ldg(gp + (size_t)u1 * 32);
        uint32_t v2 = __ldg(gp + (size_t)u2 * 32);
        uint32_t v3 = __ldg(gp + (size_t)u3 * 32);
        acc_bf16x2(a0, v0); acc_bf16x2(b0, v1);
        acc_bf16x2(a0, v2); acc_bf16x2(b0, v3);
    }
    for (; e < end; e++) {
        int u0 = __ldg(&g_colidx[e]);
        acc_bf16x2(a0, __ldg(gp + (size_t)u0 * 32));
    }
    add_f32x2(a0, b0);
    float2 f = unpack_f32x2(a0);
    float2 bb = __ldg(&((const float2*)b3)[lane]);
    float r0 = f.x * dsc + bb.x;
    float r1 = f.y * dsc + bb.y;
    float mx = fmaxf(r0, r1);
#pragma unroll
    for (int o = 16; o > 0; o >>= 1) mx = fmaxf(mx, __shfl_xor_sync(0xFFFFFFFFu, mx, o));
    float es = __expf(r0 - mx) + __expf(r1 - mx);
#pragma unroll
    for (int o = 16; o > 0; o >>= 1) es += __shfl_xor_sync(0xFFFFFFFFu, es, o);
    float lse = logf(es) + mx;
    ((float2*)out)[(size_t)warp * 32 + lane] = make_float2(r0 - lse, r1 - lse);
}

// ---------------- bf16 tensor-core GEMM ----------------
#define AS_STRIDE 68
__device__ __forceinline__ void mma_bf16(float* d, const uint32_t* a, const uint32_t* b) {
    asm volatile(
        "mma.sync.aligned.m16n8k16.row.col.f32.bf16.bf16.f32 "
        "{%0,%1,%2,%3}, {%4,%5,%6,%7}, {%8,%9}, {%0,%1,%2,%3};\n"
        : "+f"(d[0]), "+f"(d[1]), "+f"(d[2]), "+f"(d[3])
        : "r"(a[0]), "r"(a[1]), "r"(a[2]), "r"(a[3]), "r"(b[0]), "r"(b[1]));
}

template<int BN, bool EPI>
__global__ __launch_bounds__(256) void gemm_bf16_kernel(
    const uint32_t* __restrict__ A,   // bf16 pairs, row stride 64
    const float* __restrict__ W,      // fp32 [128][BN]
    const float* __restrict__ bias, const float* __restrict__ rowscale,
    uint32_t* __restrict__ C,         // bf16 pairs, row stride BN/2
    int M)
{
    constexpr int BSS = BN + 8;
    extern __shared__ uint32_t smem_u[];
    uint32_t* As = smem_u;                    // [128][AS_STRIDE]
    uint32_t* Bs = smem_u + 128 * AS_STRIDE;  // [64][BSS]

    const int t    = threadIdx.x;
    const int lane = t & 31;
    const int wid  = t >> 5;
    const int m0   = blockIdx.x * 128;
    const int g    = lane >> 2;
    const int tt   = lane & 3;
    const int wm   = wid & 3;
    const int wn   = wid >> 2;
    constexpr int NT = BN / 16;

    for (int i = t; i < 64 * (BN / 4); i += 256) {
        int kk = i / (BN / 4);
        int n4 = (i % (BN / 4)) * 4;
        float4 r0 = __ldg((const float4*)&W[(size_t)(2 * kk) * BN + n4]);
        float4 r1 = __ldg((const float4*)&W[(size_t)(2 * kk + 1) * BN + n4]);
        uint4 o;
        o.x = pack_bf16(r0.x, r1.x); o.y = pack_bf16(r0.y, r1.y);
        o.z = pack_bf16(r0.z, r1.z); o.w = pack_bf16(r0.w, r1.w);
        *(uint4*)&Bs[kk * BSS + n4] = o;
    }
    for (int i = t; i < 128 * 16; i += 256) {
        int r = i >> 4;
        int q = i & 15;
        int gm = m0 + r;
        uint4 v = make_uint4(0u, 0u, 0u, 0u);
        if (gm < M) v = __ldg(&((const uint4*)A)[(size_t)gm * 16 + q]);
        *(uint4*)&As[r * AS_STRIDE + q * 4] = v;
    }
    __syncthreads();

    float acc[2][NT][4];
#pragma unroll
    for (int i = 0; i < 2; i++)
#pragma unroll
        for (int j = 0; j < NT; j++)
#pragma unroll
            for (int c = 0; c < 4; c++) acc[i][j][c] = 0.f;

#pragma unroll
    for (int ks = 0; ks < 8; ks++) {
        int kb = ks * 8;
        uint32_t bf[NT][2];
#pragma unroll
        for (int j = 0; j < NT; j++) {
            int n = wn * (NT * 8) + j * 8 + g;
            bf[j][0] = Bs[(kb + tt) * BSS + n];
            bf[j][1] = Bs[(kb + tt + 4) * BSS + n];
        }
#pragma unroll
        for (int i = 0; i < 2; i++) {
            int m = wm * 32 + i * 16;
            uint32_t af[4];
            af[0] = As[(m + g)     * AS_STRIDE + kb + tt];
            af[1] = As[(m + g + 8) * AS_STRIDE + kb + tt];
            af[2] = As[(m + g)     * AS_STRIDE + kb + tt + 4];
            af[3] = As[(m + g + 8) * AS_STRIDE + kb + tt + 4];
#pragma unroll
            for (int j = 0; j < NT; j++) mma_bf16(acc[i][j], af, bf[j]);
        }
    }

#pragma unroll
    for (int i = 0; i < 2; i++) {
        int m_lo = m0 + wm * 32 + i * 16 + g;
        int m_hi = m_lo + 8;
        float rs_lo = 1.f, rs_hi = 1.f;
        if (EPI) {
            if (m_lo < M) rs_lo = __ldg(&rowscale[m_lo]);
            if (m_hi < M) rs_hi = __ldg(&rowscale[m_hi]);
        }
#pragma unroll
        for (int j = 0; j < NT; j++) {
            int n = wn * (NT * 8) + j * 8 + 2 * tt;
            float v0 = acc[i][j][0], v1 = acc[i][j][1];
            float v2 = acc[i][j][2], v3 = acc[i][j][3];
            if (EPI) {
                float b0 = __ldg(&bias[n]), b1 = __ldg(&bias[n + 1]);
                v0 = fmaxf(v0 + b0, 0.f) * rs_lo;
                v1 = fmaxf(v1 + b1, 0.f) * rs_lo;
                v2 = fmaxf(v2 + b0, 0.f) * rs_hi;
                v3 = fmaxf(v3 + b1, 0.f) * rs_hi;
            }
            if (m_lo < M) C[(size_t)m_lo * (BN / 2) + (n >> 1)] = pack_bf16(v0, v1);
            if (m_hi < M) C[(size_t)m_hi * (BN / 2) + (n >> 1)] = pack_bf16(v2, v3);
        }
    }
}

#define GEMM128_SMEM ((128 * AS_STRIDE + 64 * (128 + 8)) * 4)
#define GEMM64_SMEM  ((128 * AS_STRIDE + 64 * (64 + 8)) * 4)

// ---------------- launch ----------------
extern "C" void kernel_launch(void* const* d_in, const int* in_sizes, int n_in,
                              void* d_out, int out_size)
{
    const float* features = (const float*)d_in[0];
    const int*   src      = (const int*)  d_in[1];
    const int*   dst      = (const int*)  d_in[2];
    const float* W1       = (const float*)d_in[3];
    const float* b1       = (const float*)d_in[4];
    const float* W2       = (const float*)d_in[5];
    const float* b2       = (const float*)d_in[6];
    const float* W3       = (const float*)d_in[7];
    const float* b3       = (const float*)d_in[8];
    float* out = (float*)d_out;

    const int N = in_sizes[0] / DIN;   // 100000
    const int E = in_sizes[1];         // 1600000

    uint32_t* featbf; cudaGetSymbolAddress((void**)&featbf, g_featbf);
    uint32_t* aggA;   cudaGetSymbolAddress((void**)&aggA,   g_aggA);
    uint32_t* hbuf;   cudaGetSymbolAddress((void**)&hbuf,   g_h);
    uint32_t* Gbuf;   cudaGetSymbolAddress((void**)&Gbuf,   g_G);
    float*    nsrc;   cudaGetSymbolAddress((void**)&nsrc,   g_norm_src);

    static bool attr_done = false;
    if (!attr_done) {
        cudaFuncSetAttribute((const void*)gemm_bf16_kernel<128, true>,
                             cudaFuncAttributeMaxDynamicSharedMemorySize, GEMM128_SMEM);
        cudaFuncSetAttribute((const void*)gemm_bf16_kernel<64, false>,
                             cudaFuncAttributeMaxDynamicSharedMemorySize, GEMM64_SMEM);
        attr_done = true;
    }

    const int nconv = N * 16;                       // uint4s of bf16 features
    const int sc_blocks   = ((E > nconv ? E : nconv) + 255) / 256;
    const int scan_blocks = (N + 1023) / 1024;      // 98 < 148 SMs (lookback safety)
    const int spmm_blocks = (N * 32 + 255) / 256;   // warp per node
    const int gemm_blocks = (N + 127) / 128;

    // ---- CSR build: exactly 3 kernels so spmm1 stays in the profiled slot ----
    deg_kernel<<<(E + 255) / 256, 256>>>(src, dst, E);
    scan_kernel<<<scan_blocks, 256>>>(N, E);
    scatter_convert_kernel<<<sc_blocks, 256>>>(src, dst, (const float4*)features, E, N, nconv);

    // ---- layer 1 ----
    spmm128_kernel<<<spmm_blocks, 256>>>((const uint2*)featbf, (uint2*)aggA, N);
    gemm_bf16_kernel<128, true ><<<gemm_blocks, 256, GEMM128_SMEM>>>(aggA, W1, b1, nsrc, hbuf, N);

    // ---- layer 2 ----
    spmm128_kernel<<<spmm_blocks, 256>>>((const uint2*)hbuf, (uint2*)aggA, N);
    gemm_bf16_kernel<128, true ><<<gemm_blocks, 256, GEMM128_SMEM>>>(aggA, W2, b2, nsrc, hbuf, N);

    // ---- layer 3 (W-first) + fused log_softmax ----
    gemm_bf16_kernel<64, false><<<gemm_blocks, 256, GEMM64_SMEM>>>(hbuf, W3, nullptr, nullptr, Gbuf, N);
    spmm_final_kernel<<<spmm_blocks, 256>>>(Gbuf, b3, out, N);
}